// round 1
// baseline (speedup 1.0000x reference)
#include <cuda_runtime.h>
#include <cuda_bf16.h>

// Conv4d: x[4,20,20,40,40,8] (*) k[3,3,3,3,8,16] + bias -> out[4,18,18,38,38,16]
// Direct convolution, fp32 via packed fma.rn.f32x2 (2 MACs/lane/issue on sm_100a).
// Weights (41.5 KB) staged in SMEM, warp-uniform broadcast reads.
// Each thread: 2 consecutive W outputs x 16 Cout (sliding-window input reuse).

#define THREADS 128

// ---- constants of the problem shape ----
#define B_   4
#define TI   20
#define ZI   20
#define HI   40
#define WI   40
#define CI   8
#define TO   18
#define ZO   18
#define HO   38
#define WO   38
#define CO   16
#define WCHUNKS (WO / 2)                       // 19, exact
#define TOTAL_ITEMS (B_ * TO * ZO * HO * WCHUNKS)   // 935712

// strides in floats
#define XS_W  (CI)            // 8
#define XS_H  (WI * CI)       // 320
#define XS_Z  (HI * WI * CI)  // 12800
#define XS_T  (ZI * XS_Z)     // 256000
#define XS_B  (TI * XS_T)     // 5120000

__device__ __forceinline__ unsigned long long fma2(unsigned long long a,
                                                   unsigned long long b,
                                                   unsigned long long c) {
    unsigned long long d;
    asm("fma.rn.f32x2 %0, %1, %2, %3;" : "=l"(d) : "l"(a), "l"(b), "l"(c));
    return d;
}

__device__ __forceinline__ unsigned long long pack_dup(float v) {
    unsigned long long d;
    unsigned int u = __float_as_uint(v);
    asm("mov.b64 %0, {%1, %1};" : "=l"(d) : "r"(u));
    return d;
}

__device__ __forceinline__ unsigned long long pack2(float lo, float hi) {
    unsigned long long d;
    unsigned int ulo = __float_as_uint(lo), uhi = __float_as_uint(hi);
    asm("mov.b64 %0, {%1, %2};" : "=l"(d) : "r"(ulo), "r"(uhi));
    return d;
}

__global__ void __launch_bounds__(THREADS)
conv4d_kernel(const float* __restrict__ x,
              const float* __restrict__ w,
              const float* __restrict__ bias,
              float* __restrict__ out)
{
    // Weights: [81 taps][8 ci][16 co] floats == 2592 x 16B. Layout preserved:
    // ulonglong2 index (tap*8 + ci)*4 + j holds co pairs (4j,4j+1),(4j+2,4j+3).
    __shared__ ulonglong2 sw[2592];

    const ulonglong2* wg = reinterpret_cast<const ulonglong2*>(w);
    for (int i = threadIdx.x; i < 2592; i += THREADS) sw[i] = wg[i];
    __syncthreads();

    int idx = blockIdx.x * THREADS + threadIdx.x;
    if (idx >= TOTAL_ITEMS) return;

    int wc = idx % WCHUNKS; int t = idx / WCHUNKS;
    int ho = t % HO;        t /= HO;
    int zo = t % ZO;        t /= ZO;
    int to = t % TO;        int b = t / TO;
    int wo = wc * 2;

    // accumulators: 2 outputs x 8 f32x2 (16 Cout), init = bias
    unsigned long long acc[2][8];
    #pragma unroll
    for (int j = 0; j < 8; j++) {
        unsigned long long bj = pack2(bias[2 * j], bias[2 * j + 1]);
        acc[0][j] = bj;
        acc[1][j] = bj;
    }

    const float* xbase = x + b * XS_B + to * XS_T + zo * XS_Z + ho * XS_H + wo * XS_W;

    #pragma unroll 1
    for (int kt = 0; kt < 3; kt++) {
        #pragma unroll 1
        for (int kz = 0; kz < 3; kz++) {
            #pragma unroll 1
            for (int kh = 0; kh < 3; kh++) {
                const float4* xr4 = reinterpret_cast<const float4*>(
                    xbase + kt * XS_T + kz * XS_Z + kh * XS_H);

                // load 4 input positions (wo .. wo+3) x 8 ci, front-batched
                float in2[4][8];
                #pragma unroll
                for (int p = 0; p < 4; p++) {
                    float4 a = xr4[2 * p];
                    float4 c = xr4[2 * p + 1];
                    in2[p][0] = a.x; in2[p][1] = a.y; in2[p][2] = a.z; in2[p][3] = a.w;
                    in2[p][4] = c.x; in2[p][5] = c.y; in2[p][6] = c.z; in2[p][7] = c.w;
                }

                int tap3 = ((kt * 3 + kz) * 3 + kh) * 3;  // tap of kw=0
                #pragma unroll
                for (int kw = 0; kw < 3; kw++) {
                    const ulonglong2* wp = &sw[(tap3 + kw) * 32];
                    #pragma unroll
                    for (int ci = 0; ci < 8; ci++) {
                        unsigned long long v0 = pack_dup(in2[kw][ci]);
                        unsigned long long v1 = pack_dup(in2[kw + 1][ci]);
                        #pragma unroll
                        for (int j = 0; j < 4; j++) {
                            ulonglong2 W = wp[ci * 4 + j];
                            acc[0][2 * j]     = fma2(v0, W.x, acc[0][2 * j]);
                            acc[0][2 * j + 1] = fma2(v0, W.y, acc[0][2 * j + 1]);
                            acc[1][2 * j]     = fma2(v1, W.x, acc[1][2 * j]);
                            acc[1][2 * j + 1] = fma2(v1, W.y, acc[1][2 * j + 1]);
                        }
                    }
                }
            }
        }
    }

    // store: out[b][to][zo][ho][wo + o][0..15]
    int obase = ((((b * TO + to) * ZO + zo) * HO + ho) * WO + wo) * CO;
    #pragma unroll
    for (int o = 0; o < 2; o++) {
        ulonglong2* op = reinterpret_cast<ulonglong2*>(out + obase + o * CO);
        #pragma unroll
        for (int k = 0; k < 4; k++) {
            ulonglong2 v;
            v.x = acc[o][2 * k];
            v.y = acc[o][2 * k + 1];
            op[k] = v;
        }
    }
}

extern "C" void kernel_launch(void* const* d_in, const int* in_sizes, int n_in,
                              void* d_out, int out_size) {
    const float* x    = (const float*)d_in[0];
    const float* w    = (const float*)d_in[1];
    const float* bias = (const float*)d_in[2];
    float* out        = (float*)d_out;

    int blocks = (TOTAL_ITEMS + THREADS - 1) / THREADS;  // 7311
    conv4d_kernel<<<blocks, THREADS>>>(x, w, bias, out);
}